// round 17
// baseline (speedup 1.0000x reference)
#include <cuda_runtime.h>
#include <math.h>

// ---------------------------------------------------------------------------
// AttentionalGNN: L=18 layers, D=256, H=4 (head dim 64), B=2, N=1024.
// Round 17: K/V written hi/lo pre-split by the qkv GEMM epilogue; attention
// consumes split K/V directly (B-side cvt/sub removed). P buffer aliases the
// Kh buffer (smem stays 104KB, 2 blocks/SM). K double-buffer dropped (was
// neutral). GEMMs = r16 (qkv/W1 128-tile, W2 64-tile, BN fused, Wm folded).
// ---------------------------------------------------------------------------

#define BB   2
#define DD   256
#define NN   1024
#define TEN  (BB*DD*NN)
#define HTEN (BB*512*NN)

__device__ float g_q  [2*TEN];
__device__ float g_k  [2*TEN];      // K hi
__device__ float g_klo[2*TEN];      // K lo
__device__ float g_v  [2*TEN];      // V hi
__device__ float g_vlo[2*TEN];      // V lo
__device__ float g_msg[2*TEN];
__device__ float g_h  [2*HTEN];
__device__ float g_stats[2*512*2];
__device__ float g_b1eff[18*512];
__device__ float g_bnpart[2*512*64*2];

#define SZ_D  (18L*256*256)
#define SZ_1  (18L*512*512)
#define SZ_2  (18L*256*512)
#define OFF_WQ 0L
#define OFF_WK (SZ_D)
#define OFF_WV (2*SZ_D)
#define OFF_WM (3*SZ_D)
#define OFF_W1 (4*SZ_D)
#define OFF_W2 (4*SZ_D + SZ_1)
#define TOTW   (4*SZ_D + SZ_1 + SZ_2)
__device__ float g_whi[TOTW];
__device__ float g_wlo[TOTW];

__device__ __forceinline__ float to_tf32(float x) {
    unsigned u;
    asm("cvt.rna.tf32.f32 %0, %1;" : "=r"(u) : "f"(x));
    return __uint_as_float(u);
}

#define MMA_TF32(acc, af, bf)                                                  \
    asm volatile(                                                              \
        "mma.sync.aligned.m16n8k8.row.col.f32.tf32.tf32.f32 "                  \
        "{%0,%1,%2,%3}, {%4,%5,%6,%7}, {%8,%9}, {%0,%1,%2,%3};"                \
        : "+f"(acc[0]), "+f"(acc[1]), "+f"(acc[2]), "+f"(acc[3])               \
        : "r"(af[0]), "r"(af[1]), "r"(af[2]), "r"(af[3]),                      \
          "r"(bf[0]), "r"(bf[1]))

__device__ __forceinline__ void cpa16(float* dst, const float* src) {
    unsigned sa = (unsigned)__cvta_generic_to_shared(dst);
    asm volatile("cp.async.ca.shared.global [%0], [%1], 16;" :: "r"(sa), "l"(src));
}

__device__ __forceinline__ float expq(float x) {
    x = fmaxf(x, -80.f);
    float t = fmaf(x, 1.4426950408889634f, 12582912.f);
    float n = t - 12582912.f;
    float f = fmaf(x, 1.4426950408889634f, -n);
    float p = 0.0001540353039338161f;
    p = fmaf(p, f, 0.0013333558146428443f);
    p = fmaf(p, f, 0.009618129107628477f);
    p = fmaf(p, f, 0.05550410866482158f);
    p = fmaf(p, f, 0.2402265069591007f);
    p = fmaf(p, f, 0.6931471805599453f);
    p = fmaf(p, f, 1.0f);
    int ni = __float_as_int(t) - 0x4B400000;
    return __int_as_float(__float_as_int(p) + (ni << 23));
}

// ---------------------------------------------------------------------------
// Weight pre-split
// ---------------------------------------------------------------------------
__global__ __launch_bounds__(256) void presplit_kernel(
    const float* __restrict__ Wq, const float* __restrict__ Wk,
    const float* __restrict__ Wv, const float* __restrict__ Wm,
    const float* __restrict__ W1, const float* __restrict__ W2) {
    long i = ((long)blockIdx.x * 256 + threadIdx.x) * 4;
    if (i >= TOTW) return;
    const float* src; long off = i;
    if      (i < OFF_WK) { src = Wq; }
    else if (i < OFF_WV) { src = Wk; off = i - OFF_WK; }
    else if (i < OFF_WM) { src = Wv; off = i - OFF_WV; }
    else if (i < OFF_W1) { src = Wm; off = i - OFF_WM; }
    else if (i < OFF_W2) { src = W1; off = i - OFF_W1; }
    else                 { src = W2; off = i - OFF_W2; }
    float4 w = *(const float4*)(src + off);
    float4 h, l;
    h.x = to_tf32(w.x); l.x = w.x - h.x;
    h.y = to_tf32(w.y); l.y = w.y - h.y;
    h.z = to_tf32(w.z); l.z = w.z - h.z;
    h.w = to_tf32(w.w); l.w = w.w - h.w;
    *(float4*)(g_whi + i) = h;
    *(float4*)(g_wlo + i) = l;
}

// ---------------------------------------------------------------------------
// W1m precompute (unchanged).
// ---------------------------------------------------------------------------
__global__ __launch_bounds__(128) void fuse_w1m_kernel(
    const float* __restrict__ W1, const float* __restrict__ Wm) {
    __shared__ float Ah[64][36], Al[64][36];
    __shared__ float Bh[32][68], Bl[32][68];
    const int layer = blockIdx.z;
    const int n0 = blockIdx.x << 6;
    const int m0 = blockIdx.y << 6;
    const float* W1p = W1 + (size_t)layer * 262144;
    const float* Wmp = Wm + (size_t)layer * 65536;
    const int tid = threadIdx.x;
    const int warp = tid >> 5, lane = tid & 31;
    const int wm = (warp >> 1) << 5;
    const int wn = (warp & 1) << 5;
    const int g = lane >> 2, t = lane & 3;

    float acc[2][4][4];
    #pragma unroll
    for (int mi = 0; mi < 2; mi++)
        #pragma unroll
        for (int ni = 0; ni < 4; ni++)
            #pragma unroll
            for (int r = 0; r < 4; r++) acc[mi][ni][r] = 0.f;

    for (int k0 = 0; k0 < 256; k0 += 32) {
        #pragma unroll
        for (int e = tid; e < 512; e += 128) {
            int m  = e >> 3;
            int kq = (e & 7) << 2;
            float4 w = *(const float4*)&W1p[(size_t)(m0 + m) * 512 + 256 + k0 + kq];
            float wa[4] = {w.x, w.y, w.z, w.w};
            #pragma unroll
            for (int q = 0; q < 4; q++) {
                float hi = to_tf32(wa[q]);
                Ah[m][kq + q] = hi;
                Al[m][kq + q] = wa[q] - hi;
            }
        }
        #pragma unroll
        for (int e = tid; e < 512; e += 128) {
            int kk = e >> 4;
            int nq = (e & 15) << 2;
            float4 v = *(const float4*)&Wmp[(size_t)(k0 + kk) * 256 + n0 + nq];
            float va[4] = {v.x, v.y, v.z, v.w};
            #pragma unroll
            for (int q = 0; q < 4; q++) {
                float hi = to_tf32(va[q]);
                Bh[kk][nq + q] = hi;
                Bl[kk][nq + q] = va[q] - hi;
            }
        }
        __syncthreads();
        #pragma unroll
        for (int kk = 0; kk < 32; kk += 8) {
            unsigned afh[2][4], afl[2][4];
            #pragma unroll
            for (int mi = 0; mi < 2; mi++) {
                int r0 = wm + mi * 16 + g;
                afh[mi][0] = __float_as_uint(Ah[r0    ][kk + t    ]);
                afh[mi][1] = __float_as_uint(Ah[r0 + 8][kk + t    ]);
                afh[mi][2] = __float_as_uint(Ah[r0    ][kk + t + 4]);
                afh[mi][3] = __float_as_uint(Ah[r0 + 8][kk + t + 4]);
                afl[mi][0] = __float_as_uint(Al[r0    ][kk + t    ]);
                afl[mi][1] = __float_as_uint(Al[r0 + 8][kk + t    ]);
                afl[mi][2] = __float_as_uint(Al[r0    ][kk + t + 4]);
                afl[mi][3] = __float_as_uint(Al[r0 + 8][kk + t + 4]);
            }
            #pragma unroll
            for (int ni = 0; ni < 4; ni++) {
                int c = wn + ni * 8 + g;
                unsigned bh2[2] = {__float_as_uint(Bh[kk + t][c]),
                                   __float_as_uint(Bh[kk + t + 4][c])};
                unsigned bl2[2] = {__float_as_uint(Bl[kk + t][c]),
                                   __float_as_uint(Bl[kk + t + 4][c])};
                #pragma unroll
                for (int mi = 0; mi < 2; mi++) {
                    MMA_TF32(acc[mi][ni], afh[mi], bl2);
                    MMA_TF32(acc[mi][ni], afl[mi], bh2);
                    MMA_TF32(acc[mi][ni], afh[mi], bh2);
                }
            }
        }
        __syncthreads();
    }

    size_t base = OFF_W1 + (size_t)layer * 262144;
    #pragma unroll
    for (int mi = 0; mi < 2; mi++) {
        #pragma unroll
        for (int half = 0; half < 2; half++) {
            int m = m0 + wm + mi * 16 + g + half * 8;
            #pragma unroll
            for (int ni = 0; ni < 4; ni++) {
                int col = n0 + wn + ni * 8 + 2 * t;
                size_t off = base + (size_t)m * 512 + 256 + col;
                float v0 = acc[mi][ni][2 * half + 0];
                float v1 = acc[mi][ni][2 * half + 1];
                float h0 = to_tf32(v0), h1 = to_tf32(v1);
                *(float2*)(g_whi + off) = make_float2(h0, h1);
                *(float2*)(g_wlo + off) = make_float2(v0 - h0, v1 - h1);
            }
        }
    }
}

__global__ __launch_bounds__(512) void b1eff_kernel(
    const float* __restrict__ W1, const float* __restrict__ b1,
    const float* __restrict__ bm) {
    int layer = blockIdx.x;
    int m = threadIdx.x;
    const float* w = W1 + (size_t)layer * 262144 + (size_t)m * 512 + 256;
    const float* bmp = bm + layer * 256;
    float s = b1[layer * 512 + m];
    for (int o = 0; o < 256; o++) s = fmaf(w[o], bmp[o], s);
    g_b1eff[layer * 512 + m] = s;
}

// ---------------------------------------------------------------------------
// Common GEMM args.
// ---------------------------------------------------------------------------
struct GArgs {
    const float* Whi[3];
    const float* Wlo[3];
    const float* bias[3];
    const float* X0[3][2];
    const float* X1[2];
    const float* res[2];
    const float* bnp[2];
    float*       out[3][2];
    float*       out2[3][2];   // lo outputs for split_kv
    int M, K, K0, use_bn, mtiles, bn_emit, split_kv;
};

// ---------------------------------------------------------------------------
// 64x64x32 GEMM (used for W2).
// ---------------------------------------------------------------------------
#define GEMM_SMEM (13696 * 4)

__global__ __launch_bounds__(128) void gemm_tc(GArgs a) {
    extern __shared__ __align__(16) float smem[];
    const int s   = blockIdx.z;
    const int jt  = blockIdx.x;
    const int b2  = jt >> 4;
    const int n0  = (jt & 15) << 6;
    const int mat = blockIdx.y / a.mtiles;
    const int m0  = (blockIdx.y % a.mtiles) << 6;
    const int tid = threadIdx.x;
    const int warp = tid >> 5, lane = tid & 31;
    const int wm = (warp >> 1) << 5;
    const int wn = (warp & 1) << 5;
    const int g = lane >> 2, t = lane & 3;

    const int K = a.K, K0 = a.K0, M = a.M;
    const int use_bn = a.use_bn;
    const float* __restrict__ Whi = a.Whi[mat];
    const float* __restrict__ Wlo = a.Wlo[mat];
    const float* __restrict__ X0  = a.X0[mat][s];
    const float* __restrict__ X1  = a.X1[s];
    const float* __restrict__ bnp = a.bnp[s];

    float acc[2][4][4];
    #pragma unroll
    for (int mi = 0; mi < 2; mi++)
        #pragma unroll
        for (int ni = 0; ni < 4; ni++)
            #pragma unroll
            for (int r = 0; r < 4; r++) acc[mi][ni][r] = 0.f;

    auto load_tile = [&](int k0, int buf) {
        float* AHb = smem + buf * 2304;
        float* ALb = smem + 4608 + buf * 2304;
        float* BSb = smem + 9216 + buf * 2176;
        float* BNb = smem + 13568 + buf * 64;
        #pragma unroll
        for (int e = tid; e < 512; e += 128) {
            int m  = e >> 3;
            int kq = (e & 7) << 2;
            size_t woff = (size_t)(m0 + m) * K + k0 + kq;
            cpa16(AHb + m * 36 + kq, Whi + woff);
            cpa16(ALb + m * 36 + kq, Wlo + woff);
        }
        #pragma unroll
        for (int e = tid; e < 512; e += 128) {
            int kk = e >> 4;
            int nq = (e & 15) << 2;
            int k = k0 + kk;
            const float* src = (k < K0)
                ? X0 + ((size_t)b2 * K0 + k) * NN + n0 + nq
                : X1 + ((size_t)b2 * (K - K0) + (k - K0)) * NN + n0 + nq;
            cpa16(BSb + kk * 68 + nq, src);
        }
        if (use_bn && tid < 64) BNb[tid] = bnp[2 * k0 + tid];
        asm volatile("cp.async.commit_group;" ::: "memory");
    };

    const int niter = K >> 5;
    load_tile(0, 0);

    for (int it = 0; it < niter; it++) {
        const int buf = it & 1;
        if (it + 1 < niter) {
            load_tile((it + 1) << 5, buf ^ 1);
            asm volatile("cp.async.wait_group 1;" ::: "memory");
        } else {
            asm volatile("cp.async.wait_group 0;" ::: "memory");
        }
        __syncthreads();

        const float* AHb = smem + buf * 2304;
        const float* ALb = smem + 4608 + buf * 2304;
        const float* BSb = smem + 9216 + buf * 2176;
        const float* BNb = smem + 13568 + buf * 64;

        #pragma unroll
        for (int kk = 0; kk < 32; kk += 8) {
            unsigned afh[2][4], afl[2][4];
            #pragma unroll
            for (int mi = 0; mi < 2; mi++) {
                int r0 = wm + mi * 16 + g;
                afh[mi][0] = __float_as_uint(AHb[(r0    ) * 36 + kk + t    ]);
                afh[mi][1] = __float_as_uint(AHb[(r0 + 8) * 36 + kk + t    ]);
                afh[mi][2] = __float_as_uint(AHb[(r0    ) * 36 + kk + t + 4]);
                afh[mi][3] = __float_as_uint(AHb[(r0 + 8) * 36 + kk + t + 4]);
                afl[mi][0] = __float_as_uint(ALb[(r0    ) * 36 + kk + t    ]);
                afl[mi][1] = __float_as_uint(ALb[(r0 + 8) * 36 + kk + t    ]);
                afl[mi][2] = __float_as_uint(ALb[(r0    ) * 36 + kk + t + 4]);
                afl[mi][3] = __float_as_uint(ALb[(r0 + 8) * 36 + kk + t + 4]);
            }
            float sc0 = 1.f, sh0 = 0.f, sc1 = 1.f, sh1 = 0.f;
            if (use_bn) {
                sc0 = BNb[2 * (kk + t)];     sh0 = BNb[2 * (kk + t) + 1];
                sc1 = BNb[2 * (kk + t + 4)]; sh1 = BNb[2 * (kk + t + 4) + 1];
            }
            #pragma unroll
            for (int ni = 0; ni < 4; ni++) {
                int c = wn + ni * 8 + g;
                float b0 = BSb[(kk + t    ) * 68 + c];
                float b1 = BSb[(kk + t + 4) * 68 + c];
                if (use_bn) {
                    b0 = fmaxf(fmaf(b0, sc0, sh0), 0.f);
                    b1 = fmaxf(fmaf(b1, sc1, sh1), 0.f);
                }
                float h0 = to_tf32(b0), h1 = to_tf32(b1);
                unsigned bh2[2] = {__float_as_uint(h0), __float_as_uint(h1)};
                unsigned bl2[2] = {__float_as_uint(b0 - h0), __float_as_uint(b1 - h1)};
                #pragma unroll
                for (int mi = 0; mi < 2; mi++) {
                    MMA_TF32(acc[mi][ni], afh[mi], bl2);
                    MMA_TF32(acc[mi][ni], afl[mi], bh2);
                    MMA_TF32(acc[mi][ni], afh[mi], bh2);
                }
            }
        }
        __syncthreads();
    }

    const float* resp = a.res[s];
    const float* biasp = a.bias[mat];
    float* outp = a.out[mat][s];
    #pragma unroll
    for (int mi = 0; mi < 2; mi++) {
        #pragma unroll
        for (int half = 0; half < 2; half++) {
            int m = m0 + wm + mi * 16 + g + half * 8;
            float bb = biasp[m];
            #pragma unroll
            for (int ni = 0; ni < 4; ni++) {
                int col = n0 + wn + ni * 8 + 2 * t;
                size_t off = ((size_t)b2 * M + m) * NN + col;
                float2 c;
                c.x = acc[mi][ni][2 * half + 0] + bb;
                c.y = acc[mi][ni][2 * half + 1] + bb;
                if (resp) {
                    float2 r = *(const float2*)(resp + off);
                    c.x += r.x; c.y += r.y;
                }
                *(float2*)(outp + off) = c;
            }
        }
    }
}

// ---------------------------------------------------------------------------
// 128x64x32 GEMM (qkv and W1). split_kv: mats >=1 write hi/lo split outputs.
// ---------------------------------------------------------------------------
#define GEMM128_SMEM (22912 * 4)

__global__ __launch_bounds__(128) void gemm_tc128(GArgs a) {
    extern __shared__ __align__(16) float smem[];
    const int s   = blockIdx.z;
    const int jt  = blockIdx.x;
    const int b2  = jt >> 4;
    const int n0  = (jt & 15) << 6;
    const int mat = blockIdx.y / a.mtiles;
    const int m0  = (blockIdx.y % a.mtiles) << 7;
    const int tid = threadIdx.x;
    const int warp = tid >> 5, lane = tid & 31;
    const int wm = (warp >> 1) << 6;
    const int wn = (warp & 1) << 5;
    const int g = lane >> 2, t = lane & 3;

    const int K = a.K, K0 = a.K0, M = a.M;
    const float* __restrict__ Whi = a.Whi[mat];
    const float* __restrict__ Wlo = a.Wlo[mat];
    const float* __restrict__ X0  = a.X0[mat][s];
    const float* __restrict__ X1  = a.X1[s];

    float acc[4][4][4];
    #pragma unroll
    for (int mi = 0; mi < 4; mi++)
        #pragma unroll
        for (int ni = 0; ni < 4; ni++)
            #pragma unroll
            for (int r = 0; r < 4; r++) acc[mi][ni][r] = 0.f;

    auto load_tile = [&](int k0, int buf) {
        float* AHb = smem + buf * 4608;
        float* ALb = smem + 9216 + buf * 4608;
        float* BSb = smem + 18432 + buf * 2176;
        #pragma unroll
        for (int e = tid; e < 1024; e += 128) {
            int m  = e >> 3;
            int kq = (e & 7) << 2;
            size_t woff = (size_t)(m0 + m) * K + k0 + kq;
            cpa16(AHb + m * 36 + kq, Whi + woff);
            cpa16(ALb + m * 36 + kq, Wlo + woff);
        }
        #pragma unroll
        for (int e = tid; e < 512; e += 128) {
            int kk = e >> 4;
            int nq = (e & 15) << 2;
            int k = k0 + kk;
            const float* src = (k < K0)
                ? X0 + ((size_t)b2 * K0 + k) * NN + n0 + nq
                : X1 + ((size_t)b2 * (K - K0) + (k - K0)) * NN + n0 + nq;
            cpa16(BSb + kk * 68 + nq, src);
        }
        asm volatile("cp.async.commit_group;" ::: "memory");
    };

    const int niter = K >> 5;
    load_tile(0, 0);

    for (int it = 0; it < niter; it++) {
        const int buf = it & 1;
        if (it + 1 < niter) {
            load_tile((it + 1) << 5, buf ^ 1);
            asm volatile("cp.async.wait_group 1;" ::: "memory");
        } else {
            asm volatile("cp.async.wait_group 0;" ::: "memory");
        }
        __syncthreads();

        const float* AHb = smem + buf * 4608;
        const float* ALb = smem + 9216 + buf * 4608;
        const float* BSb = smem + 18432 + buf * 2176;

        #pragma unroll
        for (int kk = 0; kk < 32; kk += 8) {
            unsigned afh[4][4], afl[4][4];
            #pragma unroll
            for (int mi = 0; mi < 4; mi++) {
                int r0 = wm + mi * 16 + g;
                afh[mi][0] = __float_as_uint(AHb[(r0    ) * 36 + kk + t    ]);
                afh[mi][1] = __float_as_uint(AHb[(r0 + 8) * 36 + kk + t    ]);
                afh[mi][2] = __float_as_uint(AHb[(r0    ) * 36 + kk + t + 4]);
                afh[mi][3] = __float_as_uint(AHb[(r0 + 8) * 36 + kk + t + 4]);
                afl[mi][0] = __float_as_uint(ALb[(r0    ) * 36 + kk + t    ]);
                afl[mi][1] = __float_as_uint(ALb[(r0 + 8) * 36 + kk + t    ]);
                afl[mi][2] = __float_as_uint(ALb[(r0    ) * 36 + kk + t + 4]);
                afl[mi][3] = __float_as_uint(ALb[(r0 + 8) * 36 + kk + t + 4]);
            }
            #pragma unroll
            for (int ni = 0; ni < 4; ni++) {
                int c = wn + ni * 8 + g;
                float b0 = BSb[(kk + t    ) * 68 + c];
                float b1 = BSb[(kk + t + 4) * 68 + c];
                float h0 = to_tf32(b0), h1 = to_tf32(b1);
                unsigned bh2[2] = {__float_as_uint(h0), __float_as_uint(h1)};
                unsigned bl2[2] = {__float_as_uint(b0 - h0), __float_as_uint(b1 - h1)};
                #pragma unroll
                for (int mi = 0; mi < 4; mi++) {
                    MMA_TF32(acc[mi][ni], afh[mi], bl2);
                    MMA_TF32(acc[mi][ni], afl[mi], bh2);
                    MMA_TF32(acc[mi][ni], afh[mi], bh2);
                }
            }
        }
        __syncthreads();
    }

    const float* resp = a.res[s];
    const float* biasp = a.bias[mat];
    float* outp = a.out[mat][s];
    float* out2p = a.out2[mat][s];
    const int do_split = a.split_kv && (mat >= 1);
    float rsum[4][2] = {}, rsq[4][2] = {};
    #pragma unroll
    for (int mi = 0; mi < 4; mi++) {
        #pragma unroll
        for (int half = 0; half < 2; half++) {
            int m = m0 + wm + mi * 16 + g + half * 8;
            float bb = biasp[m];
            #pragma unroll
            for (int ni = 0; ni < 4; ni++) {
                int col = n0 + wn + ni * 8 + 2 * t;
                size_t off = ((size_t)b2 * M + m) * NN + col;
                float2 c;
                c.x = acc[mi][ni][2 * half + 0] + bb;
                c.y = acc[mi][ni][2 * half + 1] + bb;
                if (resp) {
                    float2 r = *(const float2*)(resp + off);
                    c.x += r.x; c.y += r.y;
                }
                if (do_split) {
                    float h0 = to_tf32(c.x), h1 = to_tf32(c.y);
                    *(float2*)(outp + off)  = make_float2(h0, h1);
                    *(float2*)(out2p + off) = make_float2(c.x - h0, c.y - h1);
                } else {
                    *(float2*)(outp + off) = c;
                }
                if (a.bn_emit) {
                    rsum[mi][half] += c.x + c.y;
                    rsq[mi][half] = fmaf(c.x, c.x, fmaf(c.y, c.y, rsq[mi][half]));
                }
            }
        }
    }
    if (a.bn_emit) {
        #pragma unroll
        for (int mi = 0; mi < 4; mi++)
            #pragma unroll
            for (int half = 0; half < 2; half++) {
                float s1 = rsum[mi][half], s2 = rsq[mi][half];
                s1 += __shfl_xor_sync(0xffffffffu, s1, 1);
                s2 += __shfl_xor_sync(0xffffffffu, s2, 1);
                s1 += __shfl_xor_sync(0xffffffffu, s1, 2);
                s2 += __shfl_xor_sync(0xffffffffu, s2, 2);
                if (t == 0) {
                    int m = m0 + wm + mi * 16 + g + half * 8;
                    int p = jt * 2 + (warp & 1);
                    *(float2*)&g_bnpart[(((size_t)s * 512 + m) * 64 + p) * 2] =
                        make_float2(s1, s2);
                }
            }
    }
}

// ---------------------------------------------------------------------------
// BN finalize (unchanged).
// ---------------------------------------------------------------------------
__global__ __launch_bounds__(64) void bn_finalize_kernel(
    const float* __restrict__ g1, const float* __restrict__ be1) {
    const int c = blockIdx.x;
    const int s = blockIdx.y;
    const int tid = threadIdx.x;
    float2 v = *(const float2*)&g_bnpart[(((size_t)s * 512 + c) * 64 + tid) * 2];
    float S = v.x, Q = v.y;
    #pragma unroll
    for (int w = 16; w; w >>= 1) {
        S += __shfl_xor_sync(0xffffffffu, S, w);
        Q += __shfl_xor_sync(0xffffffffu, Q, w);
    }
    __shared__ float sS[2], sQ[2];
    if ((tid & 31) == 0) { sS[tid >> 5] = S; sQ[tid >> 5] = Q; }
    __syncthreads();
    if (tid == 0) {
        S = sS[0] + sS[1];
        Q = sQ[0] + sQ[1];
        float mean = S * (1.f / 2048.f);
        float var  = Q * (1.f / 2048.f) - mean * mean;
        float rstd = rsqrtf(var + 1e-5f);
        float sc = rstd * g1[c];
        float sh = be1[c] - mean * sc;
        g_stats[(s * 512 + c) * 2 + 0] = sc;
        g_stats[(s * 512 + c) * 2 + 1] = sh;
    }
}

// ---------------------------------------------------------------------------
// Tensor-core flash attention (3xTF32), 64-q tiles, pre-split K/V.
// Buffers (4352 floats each): Qh | Ql | KP (Kh in S / P in PV / O at end) |
//   Kl | Vh | Vl  = 104448 B -> 2 blocks/SM.
// Per kt: sync, load 4 tiles (wait 0), sync, S (reads KP=Kh,Kl), red_max
// sync, softmax + P store into KP, sync, PV (reads KP=P, Vh, Vl).
// ---------------------------------------------------------------------------
#define ATTN_SMEM (6 * 4352 * 4)

__global__ __launch_bounds__(256) void attn_kernel() {
    extern __shared__ __align__(16) float sm[];
    float* Qh = sm;
    float* Ql = sm + 4352;
    float* KP = sm + 2 * 4352;
    float* Kl = sm + 3 * 4352;
    float* Vh = sm + 4 * 4352;
    float* Vl = sm + 5 * 4352;
    __shared__ float red_max[2][4][16];
    __shared__ float red_sum[2][4][16];

    const int qt = blockIdx.x;
    const int bh = blockIdx.y;
    const int s  = blockIdx.z;
    const int b2 = bh >> 2, h = bh & 3;
    const int q0 = qt << 6;
    const int tid = threadIdx.x;
    const int warp = tid >> 5, lane = tid & 31;
    const int g = lane >> 2, t = lane & 3;
    const int qw = warp >> 1, kw = warp & 1;
    const int qcol = qw << 4;
    const int kcol = kw << 5;

    size_t base = (size_t)s * TEN + (size_t)b2 * (DD * NN);
    const float* __restrict__ qp  = g_q   + base;
    const float* __restrict__ khp = g_k   + base;
    const float* __restrict__ klp = g_klo + base;
    const float* __restrict__ vhp = g_v   + base;
    const float* __restrict__ vlp = g_vlo + base;
    float* mp = g_msg + base;

    // load Q tile [d][q], fold 1/8 scale, split once
    for (int e = tid; e < 4096; e += 256) {
        int qi = e & 63, d = e >> 6;
        float v = qp[(size_t)(d * 4 + h) * NN + q0 + qi] * 0.125f;
        float hi = to_tf32(v);
        Qh[d * 68 + qi] = hi;
        Ql[d * 68 + qi] = v - hi;
    }

    float oacc[4][4] = {};
    float mi2[2] = {-1e30f, -1e30f};
    float li2[2] = {0.f, 0.f};

    for (int kt = 0; kt < 16; kt++) {
        int m0k = kt << 6;
        __syncthreads();   // prev PV done reading KP/Vh/Vl; Q store done (kt=0)
        for (int e = tid; e < 1024; e += 256) {
            int d  = e >> 4;
            int c4 = (e & 15) << 2;
            size_t goff = (size_t)(d * 4 + h) * NN + m0k + c4;
            cpa16(KP + d * 68 + c4, khp + goff);
            cpa16(Kl + d * 68 + c4, klp + goff);
            cpa16(Vh + d * 68 + c4, vhp + goff);
            cpa16(Vl + d * 68 + c4, vlp + goff);
        }
        asm volatile("cp.async.commit_group;\n\tcp.async.wait_group 0;" ::: "memory");
        __syncthreads();

        // ----- S = Q^T K (3xTF32), warp tile 16q x 32k, pre-split B -----
        float sacc[4][4] = {};
        #pragma unroll
        for (int kk = 0; kk < 64; kk += 8) {
            unsigned ah[4], al[4];
            ah[0] = __float_as_uint(Qh[(kk + t    ) * 68 + qcol + g    ]);
            ah[1] = __float_as_uint(Qh[(kk + t    ) * 68 + qcol + g + 8]);
            ah[2] = __float_as_uint(Qh[(kk + t + 4) * 68 + qcol + g    ]);
            ah[3] = __float_as_uint(Qh[(kk + t + 4) * 68 + qcol + g + 8]);
            al[0] = __float_as_uint(Ql[(kk + t    ) * 68 + qcol + g    ]);
            al[1] = __float_as_uint(Ql[(kk + t    ) * 68 + qcol + g + 8]);
            al[2] = __float_as_uint(Ql[(kk + t + 4) * 68 + qcol + g    ]);
            al[3] = __float_as_uint(Ql[(kk + t + 4) * 68 + qcol + g + 8]);
            #pragma unroll
            for (int ni = 0; ni < 4; ni++) {
                int c = kcol + ni * 8 + g;
                unsigned bh2[2] = {__float_as_uint(KP[(kk + t) * 68 + c]),
                                   __float_as_uint(KP[(kk + t + 4) * 68 + c])};
                unsigned bl2[2] = {__float_as_uint(Kl[(kk + t) * 68 + c]),
                                   __float_as_uint(Kl[(kk + t + 4) * 68 + c])};
                MMA_TF32(sacc[ni], ah, bl2);
                MMA_TF32(sacc[ni], al, bh2);
                MMA_TF32(sacc[ni], ah, bh2);
            }
        }

        // ----- online softmax -----
        float mloc[2] = {-1e30f, -1e30f};
        #pragma unroll
        for (int ni = 0; ni < 4; ni++) {
            mloc[0] = fmaxf(mloc[0], fmaxf(sacc[ni][0], sacc[ni][1]));
            mloc[1] = fmaxf(mloc[1], fmaxf(sacc[ni][2], sacc[ni][3]));
        }
        #pragma unroll
        for (int r = 0; r < 2; r++) {
            mloc[r] = fmaxf(mloc[r], __shfl_xor_sync(0xffffffffu, mloc[r], 1));
            mloc[r] = fmaxf(mloc[r], __shfl_xor_sync(0xffffffffu, mloc[r], 2));
        }
        if (t == 0) {
            red_max[kw][qw][g    ] = mloc[0];
            red_max[kw][qw][g + 8] = mloc[1];
        }
        __syncthreads();   // all warps done reading KP (S phase) -> safe to overwrite with P
        float mn[2], alpha[2];
        #pragma unroll
        for (int r = 0; r < 2; r++) {
            int row = g + r * 8;
            float mk = fmaxf(red_max[0][qw][row], red_max[1][qw][row]);
            mn[r] = fmaxf(mi2[r], mk);
            alpha[r] = expq(mi2[r] - mn[r]);
            mi2[r] = mn[r];
        }
        float rs[2] = {0.f, 0.f};
        #pragma unroll
        for (int ni = 0; ni < 4; ni++) {
            #pragma unroll
            for (int j = 0; j < 4; j++) {
                int r = j >> 1;
                float p = expq(sacc[ni][j] - mn[r]);
                sacc[ni][j] = p;
                rs[r] += p;
            }
        }
        #pragma unroll
        for (int r = 0; r < 2; r++) {
            rs[r] += __shfl_xor_sync(0xffffffffu, rs[r], 1);
            rs[r] += __shfl_xor_sync(0xffffffffu, rs[r], 2);
        }
        if (t == 0) {
            red_sum[kw][qw][g    ] = rs[0];
            red_sum[kw][qw][g + 8] = rs[1];
        }
        // stage raw P [q][k] into KP
        #pragma unroll
        for (int ni = 0; ni < 4; ni++) {
            #pragma unroll
            for (int r = 0; r < 2; r++) {
                int row = qcol + g + r * 8;
                int col = kcol + ni * 8 + 2 * t;
                *(float2*)(KP + row * 68 + col) =
                    make_float2(sacc[ni][2 * r], sacc[ni][2 * r + 1]);
            }
        }
        __syncthreads();   // P + red_sum visible

        #pragma unroll
        for (int r = 0; r < 2; r++) {
            int row = g + r * 8;
            float rstot = red_sum[0][qw][row] + red_sum[1][qw][row];
            li2[r] = li2[r] * alpha[r] + rstot;
        }
        #pragma unroll
        for (int ni = 0; ni < 4; ni++) {
            oacc[ni][0] *= alpha[0]; oacc[ni][1] *= alpha[0];
            oacc[ni][2] *= alpha[1]; oacc[ni][3] *= alpha[1];
        }

        // ----- O += P V (3xTF32), warp tile 16q x 32d, pre-split B -----
        #pragma unroll
        for (int kk = 0; kk < 64; kk += 8) {
            float a0 = KP[(qcol + g    ) * 68 + kk + t    ];
            float a1 = KP[(qcol + g + 8) * 68 + kk + t    ];
            float a2 = KP[(qcol + g    ) * 68 + kk + t + 4];
            float a3 = KP[(qcol + g + 8) * 68 + kk + t + 4];
            float ah0 = to_tf32(a0), ah1 = to_tf32(a1);
            float ah2 = to_tf32(a2), ah3 = to_tf32(a3);
            unsigned ah[4] = {__float_as_uint(ah0), __float_as_uint(ah1),
                              __float_as_uint(ah2), __float_as_uint(ah3)};
            unsigned al[4] = {__float_as_uint(a0 - ah0), __float_as_uint(a1 - ah1),
                              __float_as_uint(a2 - ah2), __float_as_uint(a3 - ah3)};
            #pragma unroll
            for (int ni = 0; ni < 4; ni++) {
                int c = kcol + ni * 8 + g;   // d column
                unsigned bh2[2] = {__float_as_uint(Vh[c * 68 + kk + t]),
                                   __float_as_uint(Vh[c * 68 + kk + t + 4])};
                unsigned bl2[2] = {__float_as_uint(Vl[c * 68 + kk + t]),
                                   __float_as_uint(Vl[c * 68 + kk + t + 4])};
                MMA_TF32(oacc[ni], ah, bl2);
                MMA_TF32(oacc[ni], al, bh2);
                MMA_TF32(oacc[ni], ah, bh2);
            }
        }
    }

    // epilogue: divide by li, stage [d][q] into KP, coalesced store
    float inv[2] = {1.f / li2[0], 1.f / li2[1]};
    __syncthreads();   // all PV reads of KP done
    #pragma unroll
    for (int ni = 0; ni < 4; ni++) {
        #pragma unroll
        for (int j = 0; j < 4; j++) {
            int r = j >> 1;
            int row_q = qcol + g + r * 8;
            int col_d = kcol + ni * 8 + 2 * t + (j & 1);
            KP[col_d * 68 + row_q] = oacc[ni][j] * inv[r];
        }
    }
    __syncthreads();
    for (int e = tid; e < 4096; e += 256) {
        int qi = e & 63, d = e >> 6;
        mp[(size_t)(d * 4 + h) * NN + q0 + qi] = KP[d * 68 + qi];
    }
}

// ---------------------------------------------------------------------------
// Host orchestration
// ---------------------------------------------------------------------------
extern "C" void kernel_launch(void* const* d_in, const int* in_sizes, int n_in,
                              void* d_out, int out_size) {
    const float* desc0 = (const float*)d_in[0];
    const float* desc1 = (const float*)d_in[1];
    const float* Wq  = (const float*)d_in[2];
    const float* bq  = (const float*)d_in[3];
    const float* Wk  = (const float*)d_in[4];
    const float* bk  = (const float*)d_in[5];
    const float* Wv  = (const float*)d_in[6];
    const float* bv  = (const float*)d_in[7];
    const float* Wm  = (const float*)d_in[8];
    const float* bm  = (const float*)d_in[9];
    const float* W1  = (const float*)d_in[10];
    const float* b1  = (const float*)d_in[11];
    const float* g1  = (const float*)d_in[12];
    const float* be1 = (const float*)d_in[13];
    const float* W2  = (const float*)d_in[14];
    const float* b2  = (const float*)d_in[15];
    float* out = (float*)d_out;

    float *qb, *kb, *klb, *vb, *vlb, *msgb, *hb, *statsb, *whi, *wlo, *b1effb;
    cudaGetSymbolAddress((void**)&qb,    g_q);
    cudaGetSymbolAddress((void**)&kb,    g_k);
    cudaGetSymbolAddress((void**)&klb,   g_klo);
    cudaGetSymbolAddress((void**)&vb,    g_v);
    cudaGetSymbolAddress((void**)&vlb,   g_vlo);
    cudaGetSymbolAddress((void**)&msgb,  g_msg);
    cudaGetSymbolAddress((void**)&hb,    g_h);
    cudaGetSymbolAddress((void**)&statsb, g_stats);
    cudaGetSymbolAddress((void**)&whi,   g_whi);
    cudaGetSymbolAddress((void**)&wlo,   g_wlo);
    cudaGetSymbolAddress((void**)&b1effb, g_b1eff);

    cudaFuncSetAttribute(attn_kernel,
                         cudaFuncAttributeMaxDynamicSharedMemorySize, ATTN_SMEM);
    cudaFuncSetAttribute(gemm_tc,
                         cudaFuncAttributeMaxDynamicSharedMemorySize, GEMM_SMEM);
    cudaFuncSetAttribute(gemm_tc128,
                         cudaFuncAttributeMaxDynamicSharedMemorySize, GEMM128_SMEM);

    presplit_kernel<<<(int)((TOTW / 4 + 255) / 256), 256>>>(Wq, Wk, Wv, Wm, W1, W2);
    fuse_w1m_kernel<<<dim3(4, 8, 18), 128>>>(W1, Wm);
    b1eff_kernel<<<18, 512>>>(W1, b1, bm);

    cudaMemcpyAsync(out + 2 * (size_t)TEN, desc0, TEN * sizeof(float),
                    cudaMemcpyDeviceToDevice, 0);
    cudaMemcpyAsync(out + 3 * (size_t)TEN, desc1, TEN * sizeof(float),
                    cudaMemcpyDeviceToDevice, 0);

    const float* xa = desc0;
    const float* xb = desc1;

    for (int i = 0; i < 18; i++) {
        const float *sa, *sb, *ra, *rb;
        float *oa, *ob;
        if (i == 0) {
            sa = xa; sb = xb; ra = desc0; rb = desc1;
            oa = out;            ob = out + (size_t)TEN;
        } else if (i == 1) {
            sa = xb; sb = xa; ra = desc0; rb = desc1;
            oa = out + 4 * (size_t)TEN; ob = out + 5 * (size_t)TEN;
        } else {
            if ((i & 1) == 0) { sa = xa; sb = xb; }
            else              { sa = xb; sb = xa; }
            ra = xa; rb = xb;
            oa = out + (size_t)(2 + 2 * i) * TEN;
            ob = oa + (size_t)TEN;
        }

        const float* Wq_hi = whi + OFF_WQ + (size_t)i * 65536;
        const float* Wq_lo = wlo + OFF_WQ + (size_t)i * 65536;
        const float* Wk_hi = whi + OFF_WK + (size_t)i * 65536;
        const float* Wk_lo = wlo + OFF_WK + (size_t)i * 65536;
        const float* Wv_hi = whi + OFF_WV + (size_t)i * 65536;
        const float* Wv_lo = wlo + OFF_WV + (size_t)i * 65536;
        const float* W1_hi = whi + OFF_W1 + (size_t)i * 262144;
        const float* W1_lo = wlo + OFF_W1 + (size_t)i * 262144;
        const float* W2_hi = whi + OFF_W2 + (size_t)i * 131072;
        const float* W2_lo = wlo + OFF_W2 + (size_t)i * 131072;
        const float* bq_i = bq + (size_t)i * 256;
        const float* bk_i = bk + (size_t)i * 256;
        const float* bv_i = bv + (size_t)i * 256;
        const float* b1e_i = b1effb + (size_t)i * 512;
        const float* b2_i = b2 + (size_t)i * 256;
        const float* g1_i = g1 + (size_t)i * 512;
        const float* be_i = be1 + (size_t)i * 512;

        GArgs ga = {};
        ga.bnp[0] = statsb; ga.bnp[1] = statsb + 1024;

        // q/k/v merged; k and v written hi/lo split
        ga.Whi[0] = Wq_hi; ga.Wlo[0] = Wq_lo; ga.bias[0] = bq_i;
        ga.Whi[1] = Wk_hi; ga.Wlo[1] = Wk_lo; ga.bias[1] = bk_i;
        ga.Whi[2] = Wv_hi; ga.Wlo[2] = Wv_lo; ga.bias[2] = bv_i;
        ga.X0[0][0] = xa; ga.X0[0][1] = xb;
        ga.X0[1][0] = sa; ga.X0[1][1] = sb;
        ga.X0[2][0] = sa; ga.X0[2][1] = sb;
        ga.out[0][0] = qb; ga.out[0][1] = qb + TEN;
        ga.out[1][0] = kb; ga.out[1][1] = kb + TEN;
        ga.out[2][0] = vb; ga.out[2][1] = vb + TEN;
        ga.out2[1][0] = klb; ga.out2[1][1] = klb + TEN;
        ga.out2[2][0] = vlb; ga.out2[2][1] = vlb + TEN;
        ga.X1[0] = ga.X1[1] = nullptr;
        ga.res[0] = ga.res[1] = nullptr;
        ga.M = 256; ga.K = 256; ga.K0 = 256; ga.use_bn = 0; ga.mtiles = 2;
        ga.bn_emit = 0; ga.split_kv = 1;
        gemm_tc128<<<dim3(32, 6, 2), 128, GEMM128_SMEM>>>(ga);
        ga.split_kv = 0;

        // attention -> g_msg
        attn_kernel<<<dim3(16, 8, 2), 256, ATTN_SMEM>>>();

        // h = [W1a | W1b*Wm] [x; attnout] + b1eff, with fused BN partials
        ga.Whi[0] = W1_hi; ga.Wlo[0] = W1_lo; ga.bias[0] = b1e_i;
        ga.X0[0][0] = xa; ga.X0[0][1] = xb;
        ga.X1[0] = msgb; ga.X1[1] = msgb + TEN;
        ga.out[0][0] = hb; ga.out[0][1] = hb + HTEN;
        ga.M = 512; ga.K = 512; ga.K0 = 256; ga.use_bn = 0; ga.mtiles = 4;
        ga.bn_emit = 1;
        gemm_tc128<<<dim3(32, 4, 2), 128, GEMM128_SMEM>>>(ga);
        ga.bn_emit = 0;

        // BN finalize
        bn_finalize_kernel<<<dim3(512, 2), 64>>>(g1_i, be_i);

        // out = res + W2 relu(BN(h)) + b2  (64x64 kernel)
        ga.Whi[0] = W2_hi; ga.Wlo[0] = W2_lo; ga.bias[0] = b2_i;
        ga.X0[0][0] = hb; ga.X0[0][1] = hb + HTEN;
        ga.X1[0] = ga.X1[1] = nullptr;
        ga.res[0] = ra; ga.res[1] = rb;
        ga.out[0][0] = oa; ga.out[0][1] = ob;
        ga.M = 256; ga.K = 512; ga.K0 = 512; ga.use_bn = 1; ga.mtiles = 4;
        gemm_tc<<<dim3(32, 4, 2), 128, GEMM_SMEM>>>(ga);
        ga.res[0] = ga.res[1] = nullptr;

        xa = oa; xb = ob;
    }
}